// round 14
// baseline (speedup 1.0000x reference)
#include <cuda_runtime.h>
#include <cuda_fp16.h>
#include <mma.h>
#include <math.h>

using namespace nvcuda;

#define BB 2
#define NN 512
#define MM 512
#define CC 64
#define O1 128
#define O2 64
#define O3 32
#define ROWS (BB*NN)
#define CNT1 524288.0f
#define CNT3 1024.0f
#define EPS_BN 1e-5f

__device__ float g_srcn[BB*NN*CC];
__device__ float g_dstn[BB*MM*CC];
__device__ float g_A[BB*NN*O1];
__device__ float g_D[BB*MM*O1];
__device__ float g_idxy[BB*MM*2];
__device__ float g_cos[BB*NN*MM];
__device__ float g_rowinv[BB*NN];
__device__ float g_colinv[BB*MM];
__device__ float g_bn1[2*O1];
__device__ float g_w1s[3*O1];
__device__ __half g_h2[(size_t)ROWS*O2*MM];
__device__ float g_stat2[2*O2];
__device__ float g_bn2[2*O2];
__device__ float g_attv[ROWS*O2];
__device__ float g_tv[ROWS*O3];
__device__ float g_stat3[2*O3];
__device__ float g_bn3[2*O3];
__device__ float g_jE[BB*NN], g_jS1[BB*NN], g_jS2[BB*NN];
__device__ float g_cE[BB*MM], g_cS1[BB*MM], g_cS2[BB*MM];
__device__ float g_cpart[8*BB*MM*4];
__device__ float g_jsc[9];
__device__ float g_redA[BB*5*O1];
__device__ float g_redD[BB*5*O1];

__global__ void k_zero() {
    int t = blockIdx.x*256 + threadIdx.x;
    if (t < BB*5*O1) { g_redA[t] = 0.f; g_redD[t] = 0.f; }
    if (t < 9) g_jsc[t] = 0.f;
    if (t < 2*O2) g_stat2[t] = 0.f;
    if (t < 2*O3) g_stat3[t] = 0.f;
}

__global__ void k_prep_dst(const float* __restrict__ RF3, const float* __restrict__ RF3i,
                           const float* __restrict__ W1) {
    int b = blockIdx.x / MM, m = blockIdx.x % MM;
    int t = threadIdx.x; // 128
    __shared__ float rf[CC], red[CC], sidx[3];
    if (t < CC) { float v = RF3[((size_t)(b*CC + t))*MM + m]; rf[t] = v; red[t] = v*v; }
    if (t >= CC && t < CC+3) sidx[t-CC] = RF3i[((size_t)(b*3 + (t-CC)))*MM + m];
    __syncthreads();
    if (t < 32) red[t] += red[t+32];
    __syncthreads();
    if (t == 0) {
        float s = 0.f;
        #pragma unroll
        for (int i = 0; i < 32; i++) s += red[i];
        red[0] = 1.0f / fmaxf(sqrtf(s), 1e-12f);
    }
    __syncthreads();
    float inv = red[0];
    if (t < CC) g_dstn[(b*MM+m)*CC + t] = rf[t]*inv;
    if (t < 2)  g_idxy[(b*MM+m)*2 + t] = sidx[t];
    float ix = sidx[0], iy = sidx[1];
    int o = t;
    float d = ix*(W1[5*O1+o] - W1[7*O1+o]) + iy*(W1[6*O1+o] - W1[8*O1+o]);
    #pragma unroll 8
    for (int c = 0; c < CC; c++) d += rf[c]*W1[(10+CC+c)*O1 + o];
    g_D[(b*MM+m)*O1 + o] = d;
}

__global__ void k_prep_src(const float* __restrict__ wxyz, const float* __restrict__ wpts,
                           const float* __restrict__ lz, const float* __restrict__ W1,
                           const float* __restrict__ b1) {
    int b = blockIdx.x / NN, n = blockIdx.x % NN;
    int t = threadIdx.x; // 128
    __shared__ float wp[CC], red[CC], sx[4];
    if (t < CC) { float v = wpts[(b*NN+n)*CC + t]; wp[t] = v; red[t] = v*v; }
    if (t >= CC && t < CC+3) sx[t-CC] = wxyz[(b*NN+n)*3 + (t-CC)];
    if (t == CC+3) sx[3] = lz[b*NN+n];
    __syncthreads();
    if (t < 32) red[t] += red[t+32];
    __syncthreads();
    if (t == 0) {
        float s = 0.f;
        #pragma unroll
        for (int i = 0; i < 32; i++) s += red[i];
        red[0] = 1.0f / fmaxf(sqrtf(s), 1e-12f);
    }
    __syncthreads();
    float inv = red[0];
    if (t < CC) g_srcn[(b*NN+n)*CC + t] = wp[t]*inv;
    float l = sx[3];
    int o = t;
    float a = sx[0]*l*W1[0*O1+o] + sx[1]*l*W1[1*O1+o] + sx[2]*l*W1[2*O1+o]
            + wp[0]*W1[3*O1+o] + wp[1]*W1[4*O1+o]
            + sx[0]*W1[7*O1+o] + sx[1]*W1[8*O1+o] + b1[o];
    #pragma unroll 8
    for (int c = 0; c < CC; c++) a += wp[c]*W1[(10+c)*O1 + o];
    g_A[(b*NN+n)*O1 + o] = a;
}

__global__ void __launch_bounds__(256) k_cos2() {
    int blk = blockIdx.x;
    int b = blk >> 6, nt = (blk >> 3) & 7, mt = blk & 7;
    __shared__ float sA[64*65];
    __shared__ float sB[64*65];
    int t = threadIdx.x;
    for (int i = t; i < 64*64; i += 256) {
        int r = i >> 6, c = i & 63;
        sA[c*65 + r] = g_srcn[(b*NN + nt*64 + r)*CC + c];
        sB[c*65 + r] = g_dstn[(b*MM + mt*64 + r)*CC + c];
    }
    __syncthreads();
    int tx = t & 15, ty = t >> 4;
    float acc[4][4];
    #pragma unroll
    for (int i = 0; i < 4; i++)
        #pragma unroll
        for (int j = 0; j < 4; j++) acc[i][j] = 0.f;
    #pragma unroll 4
    for (int k = 0; k < 64; k++) {
        float ra[4], rb[4];
        #pragma unroll
        for (int i = 0; i < 4; i++) ra[i] = sA[k*65 + ty + 16*i];
        #pragma unroll
        for (int j = 0; j < 4; j++) rb[j] = sB[k*65 + tx + 16*j];
        #pragma unroll
        for (int i = 0; i < 4; i++)
            #pragma unroll
            for (int j = 0; j < 4; j++) acc[i][j] += ra[i]*rb[j];
    }
    #pragma unroll
    for (int i = 0; i < 4; i++) {
        int n = nt*64 + ty + 16*i;
        #pragma unroll
        for (int j = 0; j < 4; j++) {
            int m = mt*64 + tx + 16*j;
            g_cos[((size_t)(b*NN+n))*MM + m] = acc[i][j];
        }
    }
}

__global__ void k_rowmax() {
    int bn = (blockIdx.x << 3) + (threadIdx.x >> 5);
    int lane = threadIdx.x & 31;
    float mx = -1e30f;
    for (int m = lane; m < MM; m += 32) mx = fmaxf(mx, g_cos[(size_t)bn*MM + m]);
    #pragma unroll
    for (int off = 16; off > 0; off >>= 1) mx = fmaxf(mx, __shfl_xor_sync(0xffffffffu, mx, off));
    if (lane == 0) g_rowinv[bn] = 1.0f/(mx + 1e-6f);
}

__global__ void k_colpart(const float* __restrict__ wxyz) {
    int blk = blockIdx.x;
    int b = blk >> 5, mc = (blk >> 3) & 3, nc = blk & 7;
    int t = threadIdx.x;
    int m = mc*128 + t;
    float ix = g_idxy[(b*MM+m)*2], iy = g_idxy[(b*MM+m)*2+1];
    float pmax = -1e30f, pE = 0.f, pS1 = 0.f, pCV = 0.f;
    for (int n = nc*64; n < nc*64+64; n++) {
        int bn = b*NN + n;
        float wx = wxyz[bn*3], wy = wxyz[bn*3+1];
        float ex = wx-ix, ey = wy-iy;
        pE += sqrtf(ex*ex + ey*ey);
        float cv = g_cos[(size_t)bn*MM + m];
        pmax = fmaxf(pmax, cv);
        pS1 += cv*g_rowinv[bn];
        pCV += cv;
    }
    int base = ((nc*BB + b)*MM + m)*4;
    g_cpart[base+0] = pmax; g_cpart[base+1] = pE;
    g_cpart[base+2] = pS1;  g_cpart[base+3] = pCV;
}

__global__ void k_colfin() {
    int id = blockIdx.x*128 + threadIdx.x;
    int b = id >> 9, m = id & (MM-1);
    float mx = -1e30f, sE = 0.f, s1 = 0.f, cvs = 0.f;
    #pragma unroll
    for (int nc = 0; nc < 8; nc++) {
        int base = ((nc*BB + b)*MM + m)*4;
        mx = fmaxf(mx, g_cpart[base]);
        sE += g_cpart[base+1]; s1 += g_cpart[base+2]; cvs += g_cpart[base+3];
    }
    float cinv = 1.0f/(mx + 1e-10f);
    g_colinv[b*MM+m] = cinv;
    g_cE[b*MM+m] = sE; g_cS1[b*MM+m] = s1; g_cS2[b*MM+m] = cvs*cinv;
}

__global__ void __launch_bounds__(256) k_rowsums(const float* __restrict__ wxyz) {
    int bn = (blockIdx.x << 3) + (threadIdx.x >> 5);
    int lane = threadIdx.x & 31;
    int b = bn >> 9;
    float wx = wxyz[bn*3], wy = wxyz[bn*3+1];
    float invr = g_rowinv[bn];
    float v[9] = {0,0,0,0,0,0,0,0,0};
    for (int m = lane; m < MM; m += 32) {
        float ix = g_idxy[(b*MM+m)*2], iy = g_idxy[(b*MM+m)*2+1];
        float ex = wx-ix, ey = wy-iy;
        float en = sqrtf(ex*ex + ey*ey);
        float cv = g_cos[(size_t)bn*MM + m];
        float s1 = cv*invr, s2 = cv*g_colinv[b*MM+m];
        v[0]+=en; v[1]+=s1; v[2]+=s2;
        v[3]+=en*en; v[4]+=s1*s1; v[5]+=s2*s2;
        v[6]+=en*s1; v[7]+=en*s2; v[8]+=s1*s2;
    }
    #pragma unroll
    for (int q = 0; q < 9; q++)
        #pragma unroll
        for (int off = 16; off > 0; off >>= 1) v[q] += __shfl_down_sync(0xffffffffu, v[q], off);
    if (lane == 0) {
        g_jE[bn] = v[0]; g_jS1[bn] = v[1]; g_jS2[bn] = v[2];
        #pragma unroll
        for (int q = 0; q < 9; q++) atomicAdd(&g_jsc[q], v[q]);
    }
}

__global__ void k_redAD() {
    int q = blockIdx.x;
    int o = threadIdx.x;
    if (q < 16) {
        int b = q >> 3, ch = q & 7;
        float sA=0.f, sA2=0.f, aE=0.f, aS1=0.f, aS2=0.f;
        for (int n = ch*64; n < ch*64+64; n++) {
            float a = g_A[(b*NN+n)*O1 + o];
            sA += a; sA2 += a*a;
            aE  += a*g_jE[b*NN+n];
            aS1 += a*g_jS1[b*NN+n];
            aS2 += a*g_jS2[b*NN+n];
        }
        atomicAdd(&g_redA[(b*5+0)*O1+o], sA);
        atomicAdd(&g_redA[(b*5+1)*O1+o], sA2);
        atomicAdd(&g_redA[(b*5+2)*O1+o], aE);
        atomicAdd(&g_redA[(b*5+3)*O1+o], aS1);
        atomicAdd(&g_redA[(b*5+4)*O1+o], aS2);
    } else {
        int b = (q-16) >> 3, ch = (q-16) & 7;
        float sD=0.f, sD2=0.f, dE=0.f, dS1=0.f, dS2=0.f;
        for (int m = ch*64; m < ch*64+64; m++) {
            float d = g_D[(b*MM+m)*O1 + o];
            sD += d; sD2 += d*d;
            dE  += d*g_cE[b*MM+m];
            dS1 += d*g_cS1[b*MM+m];
            dS2 += d*g_cS2[b*MM+m];
        }
        atomicAdd(&g_redD[(b*5+0)*O1+o], sD);
        atomicAdd(&g_redD[(b*5+1)*O1+o], sD2);
        atomicAdd(&g_redD[(b*5+2)*O1+o], dE);
        atomicAdd(&g_redD[(b*5+3)*O1+o], dS1);
        atomicAdd(&g_redD[(b*5+4)*O1+o], dS2);
    }
}

__global__ void k_fin1(const float* __restrict__ W1, const float* __restrict__ g1,
                       const float* __restrict__ be1) {
    int o = threadIdx.x;
    float w9 = W1[9*O1+o], wa = W1[138*O1+o], wb = W1[139*O1+o];
    float SH = 0.f, SH2 = 0.f;
    #pragma unroll
    for (int b = 0; b < BB; b++) {
        float sA = g_redA[(b*5+0)*O1+o], sA2 = g_redA[(b*5+1)*O1+o];
        float aE = g_redA[(b*5+2)*O1+o], aS1 = g_redA[(b*5+3)*O1+o], aS2 = g_redA[(b*5+4)*O1+o];
        float sD = g_redD[(b*5+0)*O1+o], sD2 = g_redD[(b*5+1)*O1+o];
        float dE = g_redD[(b*5+2)*O1+o], dS1 = g_redD[(b*5+3)*O1+o], dS2 = g_redD[(b*5+4)*O1+o];
        SH  += (float)MM*sA + (float)NN*sD;
        SH2 += (float)MM*sA2 + (float)NN*sD2 + 2.f*sA*sD
             + 2.f*(w9*aE + wa*aS1 + wb*aS2)
             + 2.f*(w9*dE + wa*dS1 + wb*dS2);
    }
    SH  += w9*g_jsc[0] + wa*g_jsc[1] + wb*g_jsc[2];
    SH2 += w9*w9*g_jsc[3] + wa*wa*g_jsc[4] + wb*wb*g_jsc[5]
         + 2.f*w9*wa*g_jsc[6] + 2.f*w9*wb*g_jsc[7] + 2.f*wa*wb*g_jsc[8];
    float mean = SH/CNT1;
    float var  = SH2/CNT1 - mean*mean;
    float sc = g1[o]*rsqrtf(var + EPS_BN);
    float sh = be1[o] - mean*sc;
    g_bn1[o] = sc; g_bn1[O1+o] = sh;
    g_w1s[o]      = w9*sc;
    g_w1s[O1+o]   = wa*sc;
    g_w1s[2*O1+o] = wb*sc;
}

__global__ void k_rescale() {
    int idx = blockIdx.x*256 + threadIdx.x;
    int o = idx & (O1-1);
    float sc = g_bn1[o];
    if (idx < ROWS*O1) g_A[idx] = fmaf(g_A[idx], sc, g_bn1[O1+o]);
    else               g_D[idx - ROWS*O1] *= sc;
}

// ---- wmma (HMMA) GEMM2 ----
// smem layout (bytes):
//  s_w2h : 128*64 half             @ 0       (16384)
//  s_r   : 128*136 half            @ 16384   (34816)
//  s_out : 64*132 float            @ 51200   (33792)
//  s_ess : 3*512 float             @ 84992   (6144)
//  s_stat: 128 float               @ 91136   (512)
//  s_b2  : 64 float                @ 91648   (256)
#define WSM_W2  0
#define WSM_R   16384
#define WSM_OUT 51200
#define WSM_ESS 84992
#define WSM_ST  91136
#define WSM_B2  91648
#define WSM_TOT 91904
#define LDR 136
#define LDO 132

__global__ void __launch_bounds__(256)
k_gemm2w(const float* __restrict__ W2, const float* __restrict__ b2p,
         const float* __restrict__ wxyz) {
    extern __shared__ char smc[];
    __half* s_w2h = (__half*)(smc + WSM_W2);
    __half* s_r   = (__half*)(smc + WSM_R);
    float* s_out  = (float*)(smc + WSM_OUT);
    float* s_ess  = (float*)(smc + WSM_ESS);
    float* s_stat = (float*)(smc + WSM_ST);
    float* s_b2   = (float*)(smc + WSM_B2);
    int b = blockIdx.x / NN, n = blockIdx.x % NN;
    int bn = b*NN + n;
    int t = threadIdx.x;
    int wid = t >> 5, lane = t & 31;

    for (int i = t; i < O1*O2; i += 256) s_w2h[i] = __float2half_rn(W2[i]);
    float wx = wxyz[bn*3+0], wy = wxyz[bn*3+1];
    float invr = g_rowinv[bn];
    for (int m = t; m < MM; m += 256) {
        float ix = g_idxy[(b*MM+m)*2+0], iy = g_idxy[(b*MM+m)*2+1];
        float ex = wx-ix, ey = wy-iy;
        s_ess[m] = sqrtf(ex*ex + ey*ey);
        float cv = g_cos[((size_t)bn)*MM + m];
        s_ess[MM+m]   = cv*invr;
        s_ess[2*MM+m] = cv*g_colinv[b*MM+m];
    }
    if (t < O2) s_b2[t] = b2p[t];
    if (t < 2*O2) s_stat[t] = 0.f;

    int o = t & (O1-1), half_ = t >> 7;
    float av = g_A[bn*O1 + o];
    float wn = g_w1s[o], w1s = g_w1s[O1+o], w2sv = g_w1s[2*O1+o];
    __syncthreads();

    for (int mt = 0; mt < 4; mt++) {
        // reconstruct relu(bn1(h1)) tile [128m][128k] -> fp16 smem
        const float* Dp = &g_D[(size_t)(b*MM + mt*128 + half_*64)*O1 + o];
        #pragma unroll 4
        for (int i = 0; i < 64; i++) {
            int ml = half_*64 + i, m = mt*128 + ml;
            float h = av + Dp[(size_t)i*O1] + s_ess[m]*wn + s_ess[MM+m]*w1s + s_ess[2*MM+m]*w2sv;
            s_r[ml*LDR + o] = __float2half_rn(fmaxf(h, 0.0f));
        }
        __syncthreads();

        // mma: warp wid -> m block [wid*16, wid*16+16), j blocks 0..3
        wmma::fragment<wmma::accumulator, 16, 16, 16, float> cf[4];
        #pragma unroll
        for (int jb = 0; jb < 4; jb++) wmma::fill_fragment(cf[jb], 0.0f);
        #pragma unroll
        for (int ks = 0; ks < 8; ks++) {
            wmma::fragment<wmma::matrix_a, 16, 16, 16, __half, wmma::row_major> af;
            wmma::load_matrix_sync(af, &s_r[(wid*16)*LDR + ks*16], LDR);
            #pragma unroll
            for (int jb = 0; jb < 4; jb++) {
                wmma::fragment<wmma::matrix_b, 16, 16, 16, __half, wmma::row_major> bf;
                wmma::load_matrix_sync(bf, &s_w2h[(ks*16)*O2 + jb*16], O2);
                wmma::mma_sync(cf[jb], af, bf, cf[jb]);
            }
        }
        #pragma unroll
        for (int jb = 0; jb < 4; jb++)
            wmma::store_matrix_sync(&s_out[(jb*16)*LDO + wid*16], cf[jb], LDO, wmma::mem_col_major);
        __syncthreads();

        // epilogue: +b2, fp16 store to g_h2[j][m], stats (j warp-uniform)
        #pragma unroll
        for (int i = 0; i < 16; i++) {
            int idx = t + i*256;         // 0..4095 over 64j x 64 m-pairs
            int j = idx >> 6;
            int m2 = (idx & 63)*2;
            float2 v = *(const float2*)&s_out[j*LDO + m2];
            float bb = s_b2[j];
            float v0 = v.x + bb, v1 = v.y + bb;
            *(__half2*)&g_h2[((size_t)bn*O2 + j)*MM + mt*128 + m2] = __floats2half2_rn(v0, v1);
            float s = v0 + v1, q = v0*v0 + v1*v1;
            #pragma unroll
            for (int off = 16; off > 0; off >>= 1) {
                s += __shfl_down_sync(0xffffffffu, s, off);
                q += __shfl_down_sync(0xffffffffu, q, off);
            }
            if (lane == 0) {
                atomicAdd(&s_stat[j], s);
                atomicAdd(&s_stat[O2+j], q);
            }
        }
        __syncthreads();
    }
    if (t < 2*O2) atomicAdd(&g_stat2[t], s_stat[t]);
}

__global__ void k_fin2(const float* __restrict__ g2, const float* __restrict__ be2) {
    int j = threadIdx.x;
    float mean = g_stat2[j]/CNT1;
    float var  = g_stat2[O2+j]/CNT1 - mean*mean;
    float sc = g2[j]*rsqrtf(var + EPS_BN);
    g_bn2[j] = sc; g_bn2[O2+j] = be2[j] - mean*sc;
}

__global__ void k_att() {
    int bn = blockIdx.x;
    int t = threadIdx.x; // 512
    __shared__ float sc2[O2], sh2[O2], aw[MM], red[512];
    if (t < O2) { sc2[t] = g_bn2[t]; sh2[t] = g_bn2[O2+t]; }
    __syncthreads();
    float mx = -1e30f;
    #pragma unroll 8
    for (int j = 0; j < O2; j++) {
        float v = __half2float(g_h2[((size_t)bn*O2 + j)*MM + t]);
        float y = fmaxf(fmaf(sc2[j], v, sh2[j]), 0.0f);
        mx = fmaxf(mx, y);
    }
    red[t] = mx;
    __syncthreads();
    for (int s = 256; s > 0; s >>= 1) { if (t < s) red[t] = fmaxf(red[t], red[t+s]); __syncthreads(); }
    float mall = red[0];
    __syncthreads();
    float e = expf(mx - mall);
    red[t] = e;
    __syncthreads();
    for (int s = 256; s > 0; s >>= 1) { if (t < s) red[t] += red[t+s]; __syncthreads(); }
    float inv = 1.0f/red[0];
    aw[t] = e*inv;
    __syncthreads();

    int w = t >> 5, lane = t & 31;
    int j0 = w*4;
    float scl[4], shl[4], acc[4];
    #pragma unroll
    for (int q = 0; q < 4; q++) { scl[q]=sc2[j0+q]; shl[q]=sh2[j0+q]; acc[q]=0.f; }
    for (int mt = 0; mt < MM; mt += 64) {
        int m = mt + lane*2;
        float aw0 = aw[m], aw1 = aw[m+1];
        #pragma unroll
        for (int q = 0; q < 4; q++) {
            __half2 hv = *(const __half2*)&g_h2[((size_t)bn*O2 + j0+q)*MM + m];
            float2 fv = __half22float2(hv);
            float y0 = fmaxf(fmaf(scl[q], fv.x, shl[q]), 0.0f);
            float y1 = fmaxf(fmaf(scl[q], fv.y, shl[q]), 0.0f);
            acc[q] += aw0*y0 + aw1*y1;
        }
    }
    #pragma unroll
    for (int q = 0; q < 4; q++) {
        float s = acc[q];
        #pragma unroll
        for (int off = 16; off > 0; off >>= 1) s += __shfl_down_sync(0xffffffffu, s, off);
        if (lane == 0) g_attv[bn*O2 + j0+q] = s;
    }
}

__global__ void k_head(const float* __restrict__ M1w, const float* __restrict__ M1b) {
    int bn = blockIdx.x;
    int j = threadIdx.x;
    float s = M1b[j];
    #pragma unroll 8
    for (int c = 0; c < O2; c++) s += g_attv[bn*O2+c]*M1w[c*O3+j];
    g_tv[bn*O3+j] = s;
    atomicAdd(&g_stat3[j], s);
    atomicAdd(&g_stat3[O3+j], s*s);
}

__global__ void k_fin3(const float* __restrict__ M1g, const float* __restrict__ M1be) {
    int j = threadIdx.x;
    float mean = g_stat3[j]/CNT3;
    float var  = g_stat3[O3+j]/CNT3 - mean*mean;
    float sc = M1g[j]*rsqrtf(var + EPS_BN);
    g_bn3[j] = sc; g_bn3[O3+j] = M1be[j] - mean*sc;
}

__global__ void k_final(const float* __restrict__ M2w, const float* __restrict__ M2b,
                        float* __restrict__ out) {
    int bn = blockIdx.x*128 + threadIdx.x;
    float l0 = M2b[0], l1 = M2b[1];
    #pragma unroll 8
    for (int c = 0; c < O3; c++) {
        float y = fmaxf(fmaf(g_bn3[c], g_tv[bn*O3+c], g_bn3[O3+c]), 0.0f);
        l0 += y*M2w[c*2+0];
        l1 += y*M2w[c*2+1];
    }
    out[bn*2+0] = l0;
    out[bn*2+1] = l1;
}

extern "C" void kernel_launch(void* const* d_in, const int* in_sizes, int n_in,
                              void* d_out, int out_size) {
    const float* wxyz = (const float*)d_in[0];
    const float* wpts = (const float*)d_in[1];
    const float* RF3  = (const float*)d_in[2];
    const float* RF3i = (const float*)d_in[3];
    const float* lz   = (const float*)d_in[4];
    const float* W1   = (const float*)d_in[5];
    const float* b1   = (const float*)d_in[6];
    const float* g1   = (const float*)d_in[7];
    const float* be1  = (const float*)d_in[8];
    const float* W2   = (const float*)d_in[9];
    const float* b2   = (const float*)d_in[10];
    const float* g2   = (const float*)d_in[11];
    const float* be2  = (const float*)d_in[12];
    const float* M1w  = (const float*)d_in[13];
    const float* M1b  = (const float*)d_in[14];
    const float* M1g  = (const float*)d_in[15];
    const float* M1be = (const float*)d_in[16];
    const float* M2w  = (const float*)d_in[17];
    const float* M2b  = (const float*)d_in[18];
    float* out = (float*)d_out;

    cudaFuncSetAttribute(k_gemm2w, cudaFuncAttributeMaxDynamicSharedMemorySize, WSM_TOT);

    k_zero<<<10, 256>>>();
    k_prep_dst<<<BB*MM, 128>>>(RF3, RF3i, W1);
    k_prep_src<<<BB*NN, 128>>>(wxyz, wpts, lz, W1, b1);
    k_cos2<<<BB*64, 256>>>();
    k_rowmax<<<ROWS/8, 256>>>();
    k_colpart<<<64, 128>>>(wxyz);
    k_colfin<<<8, 128>>>();
    k_rowsums<<<ROWS/8, 256>>>(wxyz);
    k_redAD<<<32, 128>>>();
    k_fin1<<<1, 128>>>(W1, g1, be1);
    k_rescale<<<(2*ROWS*O1)/256, 256>>>();
    k_gemm2w<<<BB*NN, 256, WSM_TOT>>>(W2, b2, wxyz);
    k_fin2<<<1, 64>>>(g2, be2);
    k_att<<<BB*NN, 512>>>();
    k_head<<<ROWS, 32>>>(M1w, M1b);
    k_fin3<<<1, 32>>>(M1g, M1be);
    k_final<<<ROWS/128, 128>>>(M2w, M2b, out);
}

// round 15
// speedup vs baseline: 1.1299x; 1.1299x over previous
#include <cuda_runtime.h>
#include <cuda_fp16.h>
#include <mma.h>
#include <math.h>

using namespace nvcuda;

#define BB 2
#define NN 512
#define MM 512
#define CC 64
#define O1 128
#define O2 64
#define O3 32
#define ROWS (BB*NN)
#define CNT1 524288.0f
#define CNT3 1024.0f
#define EPS_BN 1e-5f

__device__ float g_srcn[BB*NN*CC];
__device__ float g_dstn[BB*MM*CC];
__device__ float g_A[BB*NN*O1];
__device__ float g_D[BB*MM*O1];
__device__ float g_idxy[BB*MM*2];
__device__ float g_cos[BB*NN*MM];
__device__ float g_rowinv[BB*NN];
__device__ float g_colinv[BB*MM];
__device__ float g_bn1[2*O1];
__device__ float g_w1s[3*O1];
__device__ __half g_h2[(size_t)ROWS*O2*MM];
__device__ float g_stat2[2*O2];
__device__ float g_bn2[2*O2];
__device__ float g_attv[ROWS*O2];
__device__ float g_tv[ROWS*O3];
__device__ float g_stat3[2*O3];
__device__ float g_bn3[2*O3];
__device__ float g_jE[BB*NN], g_jS1[BB*NN], g_jS2[BB*NN];
__device__ float g_cE[BB*MM], g_cS1[BB*MM], g_cS2[BB*MM];
__device__ float g_cpart[8*BB*MM*4];
__device__ float g_jsc[9];
__device__ float g_redA[BB*5*O1];
__device__ float g_redD[BB*5*O1];

__global__ void k_zero() {
    int t = blockIdx.x*256 + threadIdx.x;
    if (t < BB*5*O1) { g_redA[t] = 0.f; g_redD[t] = 0.f; }
    if (t < 9) g_jsc[t] = 0.f;
    if (t < 2*O2) g_stat2[t] = 0.f;
    if (t < 2*O3) g_stat3[t] = 0.f;
}

__global__ void k_prep_dst(const float* __restrict__ RF3, const float* __restrict__ RF3i,
                           const float* __restrict__ W1) {
    int b = blockIdx.x / MM, m = blockIdx.x % MM;
    int t = threadIdx.x; // 128
    __shared__ float rf[CC], red[CC], sidx[3];
    if (t < CC) { float v = RF3[((size_t)(b*CC + t))*MM + m]; rf[t] = v; red[t] = v*v; }
    if (t >= CC && t < CC+3) sidx[t-CC] = RF3i[((size_t)(b*3 + (t-CC)))*MM + m];
    __syncthreads();
    if (t < 32) red[t] += red[t+32];
    __syncthreads();
    if (t == 0) {
        float s = 0.f;
        #pragma unroll
        for (int i = 0; i < 32; i++) s += red[i];
        red[0] = 1.0f / fmaxf(sqrtf(s), 1e-12f);
    }
    __syncthreads();
    float inv = red[0];
    if (t < CC) g_dstn[(b*MM+m)*CC + t] = rf[t]*inv;
    if (t < 2)  g_idxy[(b*MM+m)*2 + t] = sidx[t];
    float ix = sidx[0], iy = sidx[1];
    int o = t;
    float d = ix*(W1[5*O1+o] - W1[7*O1+o]) + iy*(W1[6*O1+o] - W1[8*O1+o]);
    #pragma unroll 8
    for (int c = 0; c < CC; c++) d += rf[c]*W1[(10+CC+c)*O1 + o];
    g_D[(b*MM+m)*O1 + o] = d;
}

__global__ void k_prep_src(const float* __restrict__ wxyz, const float* __restrict__ wpts,
                           const float* __restrict__ lz, const float* __restrict__ W1,
                           const float* __restrict__ b1) {
    int b = blockIdx.x / NN, n = blockIdx.x % NN;
    int t = threadIdx.x; // 128
    __shared__ float wp[CC], red[CC], sx[4];
    if (t < CC) { float v = wpts[(b*NN+n)*CC + t]; wp[t] = v; red[t] = v*v; }
    if (t >= CC && t < CC+3) sx[t-CC] = wxyz[(b*NN+n)*3 + (t-CC)];
    if (t == CC+3) sx[3] = lz[b*NN+n];
    __syncthreads();
    if (t < 32) red[t] += red[t+32];
    __syncthreads();
    if (t == 0) {
        float s = 0.f;
        #pragma unroll
        for (int i = 0; i < 32; i++) s += red[i];
        red[0] = 1.0f / fmaxf(sqrtf(s), 1e-12f);
    }
    __syncthreads();
    float inv = red[0];
    if (t < CC) g_srcn[(b*NN+n)*CC + t] = wp[t]*inv;
    float l = sx[3];
    int o = t;
    float a = sx[0]*l*W1[0*O1+o] + sx[1]*l*W1[1*O1+o] + sx[2]*l*W1[2*O1+o]
            + wp[0]*W1[3*O1+o] + wp[1]*W1[4*O1+o]
            + sx[0]*W1[7*O1+o] + sx[1]*W1[8*O1+o] + b1[o];
    #pragma unroll 8
    for (int c = 0; c < CC; c++) a += wp[c]*W1[(10+c)*O1 + o];
    g_A[(b*NN+n)*O1 + o] = a;
}

__global__ void __launch_bounds__(256) k_cos2() {
    int blk = blockIdx.x;
    int b = blk >> 6, nt = (blk >> 3) & 7, mt = blk & 7;
    __shared__ float sA[64*65];
    __shared__ float sB[64*65];
    int t = threadIdx.x;
    for (int i = t; i < 64*64; i += 256) {
        int r = i >> 6, c = i & 63;
        sA[c*65 + r] = g_srcn[(b*NN + nt*64 + r)*CC + c];
        sB[c*65 + r] = g_dstn[(b*MM + mt*64 + r)*CC + c];
    }
    __syncthreads();
    int tx = t & 15, ty = t >> 4;
    float acc[4][4];
    #pragma unroll
    for (int i = 0; i < 4; i++)
        #pragma unroll
        for (int j = 0; j < 4; j++) acc[i][j] = 0.f;
    #pragma unroll 4
    for (int k = 0; k < 64; k++) {
        float ra[4], rb[4];
        #pragma unroll
        for (int i = 0; i < 4; i++) ra[i] = sA[k*65 + ty + 16*i];
        #pragma unroll
        for (int j = 0; j < 4; j++) rb[j] = sB[k*65 + tx + 16*j];
        #pragma unroll
        for (int i = 0; i < 4; i++)
            #pragma unroll
            for (int j = 0; j < 4; j++) acc[i][j] += ra[i]*rb[j];
    }
    #pragma unroll
    for (int i = 0; i < 4; i++) {
        int n = nt*64 + ty + 16*i;
        #pragma unroll
        for (int j = 0; j < 4; j++) {
            int m = mt*64 + tx + 16*j;
            g_cos[((size_t)(b*NN+n))*MM + m] = acc[i][j];
        }
    }
}

__global__ void k_rowmax() {
    int bn = (blockIdx.x << 3) + (threadIdx.x >> 5);
    int lane = threadIdx.x & 31;
    float mx = -1e30f;
    for (int m = lane; m < MM; m += 32) mx = fmaxf(mx, g_cos[(size_t)bn*MM + m]);
    #pragma unroll
    for (int off = 16; off > 0; off >>= 1) mx = fmaxf(mx, __shfl_xor_sync(0xffffffffu, mx, off));
    if (lane == 0) g_rowinv[bn] = 1.0f/(mx + 1e-6f);
}

__global__ void k_colpart(const float* __restrict__ wxyz) {
    int blk = blockIdx.x;
    int b = blk >> 5, mc = (blk >> 3) & 3, nc = blk & 7;
    int t = threadIdx.x;
    int m = mc*128 + t;
    float ix = g_idxy[(b*MM+m)*2], iy = g_idxy[(b*MM+m)*2+1];
    float pmax = -1e30f, pE = 0.f, pS1 = 0.f, pCV = 0.f;
    for (int n = nc*64; n < nc*64+64; n++) {
        int bn = b*NN + n;
        float wx = wxyz[bn*3], wy = wxyz[bn*3+1];
        float ex = wx-ix, ey = wy-iy;
        pE += sqrtf(ex*ex + ey*ey);
        float cv = g_cos[(size_t)bn*MM + m];
        pmax = fmaxf(pmax, cv);
        pS1 += cv*g_rowinv[bn];
        pCV += cv;
    }
    int base = ((nc*BB + b)*MM + m)*4;
    g_cpart[base+0] = pmax; g_cpart[base+1] = pE;
    g_cpart[base+2] = pS1;  g_cpart[base+3] = pCV;
}

__global__ void k_colfin() {
    int id = blockIdx.x*128 + threadIdx.x;
    int b = id >> 9, m = id & (MM-1);
    float mx = -1e30f, sE = 0.f, s1 = 0.f, cvs = 0.f;
    #pragma unroll
    for (int nc = 0; nc < 8; nc++) {
        int base = ((nc*BB + b)*MM + m)*4;
        mx = fmaxf(mx, g_cpart[base]);
        sE += g_cpart[base+1]; s1 += g_cpart[base+2]; cvs += g_cpart[base+3];
    }
    float cinv = 1.0f/(mx + 1e-10f);
    g_colinv[b*MM+m] = cinv;
    g_cE[b*MM+m] = sE; g_cS1[b*MM+m] = s1; g_cS2[b*MM+m] = cvs*cinv;
}

__global__ void __launch_bounds__(256) k_rowsums(const float* __restrict__ wxyz) {
    int bn = (blockIdx.x << 3) + (threadIdx.x >> 5);
    int lane = threadIdx.x & 31;
    int b = bn >> 9;
    float wx = wxyz[bn*3], wy = wxyz[bn*3+1];
    float invr = g_rowinv[bn];
    float v[9] = {0,0,0,0,0,0,0,0,0};
    for (int m = lane; m < MM; m += 32) {
        float ix = g_idxy[(b*MM+m)*2], iy = g_idxy[(b*MM+m)*2+1];
        float ex = wx-ix, ey = wy-iy;
        float en = sqrtf(ex*ex + ey*ey);
        float cv = g_cos[(size_t)bn*MM + m];
        float s1 = cv*invr, s2 = cv*g_colinv[b*MM+m];
        v[0]+=en; v[1]+=s1; v[2]+=s2;
        v[3]+=en*en; v[4]+=s1*s1; v[5]+=s2*s2;
        v[6]+=en*s1; v[7]+=en*s2; v[8]+=s1*s2;
    }
    #pragma unroll
    for (int q = 0; q < 9; q++)
        #pragma unroll
        for (int off = 16; off > 0; off >>= 1) v[q] += __shfl_down_sync(0xffffffffu, v[q], off);
    if (lane == 0) {
        g_jE[bn] = v[0]; g_jS1[bn] = v[1]; g_jS2[bn] = v[2];
        #pragma unroll
        for (int q = 0; q < 9; q++) atomicAdd(&g_jsc[q], v[q]);
    }
}

__global__ void k_redAD() {
    int q = blockIdx.x;
    int o = threadIdx.x;
    if (q < 16) {
        int b = q >> 3, ch = q & 7;
        float sA=0.f, sA2=0.f, aE=0.f, aS1=0.f, aS2=0.f;
        for (int n = ch*64; n < ch*64+64; n++) {
            float a = g_A[(b*NN+n)*O1 + o];
            sA += a; sA2 += a*a;
            aE  += a*g_jE[b*NN+n];
            aS1 += a*g_jS1[b*NN+n];
            aS2 += a*g_jS2[b*NN+n];
        }
        atomicAdd(&g_redA[(b*5+0)*O1+o], sA);
        atomicAdd(&g_redA[(b*5+1)*O1+o], sA2);
        atomicAdd(&g_redA[(b*5+2)*O1+o], aE);
        atomicAdd(&g_redA[(b*5+3)*O1+o], aS1);
        atomicAdd(&g_redA[(b*5+4)*O1+o], aS2);
    } else {
        int b = (q-16) >> 3, ch = (q-16) & 7;
        float sD=0.f, sD2=0.f, dE=0.f, dS1=0.f, dS2=0.f;
        for (int m = ch*64; m < ch*64+64; m++) {
            float d = g_D[(b*MM+m)*O1 + o];
            sD += d; sD2 += d*d;
            dE  += d*g_cE[b*MM+m];
            dS1 += d*g_cS1[b*MM+m];
            dS2 += d*g_cS2[b*MM+m];
        }
        atomicAdd(&g_redD[(b*5+0)*O1+o], sD);
        atomicAdd(&g_redD[(b*5+1)*O1+o], sD2);
        atomicAdd(&g_redD[(b*5+2)*O1+o], dE);
        atomicAdd(&g_redD[(b*5+3)*O1+o], dS1);
        atomicAdd(&g_redD[(b*5+4)*O1+o], dS2);
    }
}

__global__ void k_fin1(const float* __restrict__ W1, const float* __restrict__ g1,
                       const float* __restrict__ be1) {
    int o = threadIdx.x;
    float w9 = W1[9*O1+o], wa = W1[138*O1+o], wb = W1[139*O1+o];
    float SH = 0.f, SH2 = 0.f;
    #pragma unroll
    for (int b = 0; b < BB; b++) {
        float sA = g_redA[(b*5+0)*O1+o], sA2 = g_redA[(b*5+1)*O1+o];
        float aE = g_redA[(b*5+2)*O1+o], aS1 = g_redA[(b*5+3)*O1+o], aS2 = g_redA[(b*5+4)*O1+o];
        float sD = g_redD[(b*5+0)*O1+o], sD2 = g_redD[(b*5+1)*O1+o];
        float dE = g_redD[(b*5+2)*O1+o], dS1 = g_redD[(b*5+3)*O1+o], dS2 = g_redD[(b*5+4)*O1+o];
        SH  += (float)MM*sA + (float)NN*sD;
        SH2 += (float)MM*sA2 + (float)NN*sD2 + 2.f*sA*sD
             + 2.f*(w9*aE + wa*aS1 + wb*aS2)
             + 2.f*(w9*dE + wa*dS1 + wb*dS2);
    }
    SH  += w9*g_jsc[0] + wa*g_jsc[1] + wb*g_jsc[2];
    SH2 += w9*w9*g_jsc[3] + wa*wa*g_jsc[4] + wb*wb*g_jsc[5]
         + 2.f*w9*wa*g_jsc[6] + 2.f*w9*wb*g_jsc[7] + 2.f*wa*wb*g_jsc[8];
    float mean = SH/CNT1;
    float var  = SH2/CNT1 - mean*mean;
    float sc = g1[o]*rsqrtf(var + EPS_BN);
    float sh = be1[o] - mean*sc;
    g_bn1[o] = sc; g_bn1[O1+o] = sh;
    g_w1s[o]      = w9*sc;
    g_w1s[O1+o]   = wa*sc;
    g_w1s[2*O1+o] = wb*sc;
}

__global__ void k_rescale() {
    int idx = blockIdx.x*256 + threadIdx.x;
    int o = idx & (O1-1);
    float sc = g_bn1[o];
    if (idx < ROWS*O1) g_A[idx] = fmaf(g_A[idx], sc, g_bn1[O1+o]);
    else               g_D[idx - ROWS*O1] *= sc;
}

// ---- wmma (HMMA) GEMM2, lean epilogue ----
#define WSM_W2  0
#define WSM_R   16384
#define WSM_OUT 51200
#define WSM_ESS 84992
#define WSM_ST  91136
#define WSM_B2  91648
#define WSM_TOT 91904
#define LDR 136
#define LDO 132

__global__ void __launch_bounds__(256)
k_gemm2w(const float* __restrict__ W2, const float* __restrict__ b2p,
         const float* __restrict__ wxyz) {
    extern __shared__ char smc[];
    __half* s_w2h = (__half*)(smc + WSM_W2);
    __half* s_r   = (__half*)(smc + WSM_R);
    float* s_out  = (float*)(smc + WSM_OUT);
    float* s_ess  = (float*)(smc + WSM_ESS);
    float* s_stat = (float*)(smc + WSM_ST);
    float* s_b2   = (float*)(smc + WSM_B2);
    int b = blockIdx.x / NN, n = blockIdx.x % NN;
    int bn = b*NN + n;
    int t = threadIdx.x;
    int wid = t >> 5;

    for (int i = t; i < O1*O2; i += 256) s_w2h[i] = __float2half_rn(W2[i]);
    float wx = wxyz[bn*3+0], wy = wxyz[bn*3+1];
    float invr = g_rowinv[bn];
    for (int m = t; m < MM; m += 256) {
        float ix = g_idxy[(b*MM+m)*2+0], iy = g_idxy[(b*MM+m)*2+1];
        float ex = wx-ix, ey = wy-iy;
        s_ess[m] = sqrtf(ex*ex + ey*ey);
        float cv = g_cos[((size_t)bn)*MM + m];
        s_ess[MM+m]   = cv*invr;
        s_ess[2*MM+m] = cv*g_colinv[b*MM+m];
    }
    if (t < O2) s_b2[t] = b2p[t];
    if (t < 2*O2) s_stat[t] = 0.f;

    int o = t & (O1-1), half_ = t >> 7;
    float av = g_A[bn*O1 + o];
    float wn = g_w1s[o], w1s = g_w1s[O1+o], w2sv = g_w1s[2*O1+o];
    int js = t & 63, grp = t >> 6;
    float ssum = 0.f, ssq = 0.f;
    __syncthreads();
    float bbj = s_b2[js];

    for (int mt = 0; mt < 4; mt++) {
        const float* Dp = &g_D[(size_t)(b*MM + mt*128 + half_*64)*O1 + o];
        #pragma unroll 4
        for (int i = 0; i < 64; i++) {
            int ml = half_*64 + i, m = mt*128 + ml;
            float h = av + Dp[(size_t)i*O1] + s_ess[m]*wn + s_ess[MM+m]*w1s + s_ess[2*MM+m]*w2sv;
            s_r[ml*LDR + o] = __float2half_rn(fmaxf(h, 0.0f));
        }
        __syncthreads();

        wmma::fragment<wmma::accumulator, 16, 16, 16, float> cf[4];
        #pragma unroll
        for (int jb = 0; jb < 4; jb++) wmma::fill_fragment(cf[jb], 0.0f);
        #pragma unroll
        for (int ks = 0; ks < 8; ks++) {
            wmma::fragment<wmma::matrix_a, 16, 16, 16, __half, wmma::row_major> af;
            wmma::load_matrix_sync(af, &s_r[(wid*16)*LDR + ks*16], LDR);
            #pragma unroll
            for (int jb = 0; jb < 4; jb++) {
                wmma::fragment<wmma::matrix_b, 16, 16, 16, __half, wmma::row_major> bf;
                wmma::load_matrix_sync(bf, &s_w2h[(ks*16)*O2 + jb*16], O2);
                wmma::mma_sync(cf[jb], af, bf, cf[jb]);
            }
        }
        #pragma unroll
        for (int jb = 0; jb < 4; jb++)
            wmma::store_matrix_sync(&s_out[(jb*16)*LDO + wid*16], cf[jb], LDO, wmma::mem_col_major);
        __syncthreads();

        // pass 1: coalesced +b2 store to g_h2 (j warp-uniform)
        #pragma unroll
        for (int i = 0; i < 16; i++) {
            int idx = t + i*256;
            int j = idx >> 6;
            int m2 = (idx & 63)*2;
            float2 v = *(const float2*)&s_out[j*LDO + m2];
            float bb = s_b2[j];
            *(__half2*)&g_h2[((size_t)bn*O2 + j)*MM + mt*128 + m2] = __floats2half2_rn(v.x + bb, v.y + bb);
        }
        // pass 2: register-accumulated stats for fixed j=js
        #pragma unroll
        for (int ii = 0; ii < 16; ii++) {
            int m2 = grp*32 + ii*2;
            float2 v = *(const float2*)&s_out[js*LDO + m2];
            float v0 = v.x + bbj, v1 = v.y + bbj;
            ssum += v0 + v1; ssq += v0*v0 + v1*v1;
        }
        __syncthreads();
    }
    atomicAdd(&s_stat[js], ssum);
    atomicAdd(&s_stat[O2+js], ssq);
    __syncthreads();
    if (t < 2*O2) atomicAdd(&g_stat2[t], s_stat[t]);
}

__global__ void k_fin2(const float* __restrict__ g2, const float* __restrict__ be2) {
    int j = threadIdx.x;
    float mean = g_stat2[j]/CNT1;
    float var  = g_stat2[O2+j]/CNT1 - mean*mean;
    float sc = g2[j]*rsqrtf(var + EPS_BN);
    g_bn2[j] = sc; g_bn2[O2+j] = be2[j] - mean*sc;
}

__global__ void k_att() {
    int bn = blockIdx.x;
    int t = threadIdx.x; // 512
    __shared__ float sc2[O2], sh2[O2], aw[MM], red[512];
    if (t < O2) { sc2[t] = g_bn2[t]; sh2[t] = g_bn2[O2+t]; }
    __syncthreads();
    float mx = -1e30f;
    #pragma unroll 8
    for (int j = 0; j < O2; j++) {
        float v = __half2float(g_h2[((size_t)bn*O2 + j)*MM + t]);
        float y = fmaxf(fmaf(sc2[j], v, sh2[j]), 0.0f);
        mx = fmaxf(mx, y);
    }
    red[t] = mx;
    __syncthreads();
    for (int s = 256; s > 0; s >>= 1) { if (t < s) red[t] = fmaxf(red[t], red[t+s]); __syncthreads(); }
    float mall = red[0];
    __syncthreads();
    float e = expf(mx - mall);
    red[t] = e;
    __syncthreads();
    for (int s = 256; s > 0; s >>= 1) { if (t < s) red[t] += red[t+s]; __syncthreads(); }
    float inv = 1.0f/red[0];
    aw[t] = e*inv;
    __syncthreads();

    int w = t >> 5, lane = t & 31;
    int j0 = w*4;
    float scl[4], shl[4], acc[4];
    #pragma unroll
    for (int q = 0; q < 4; q++) { scl[q]=sc2[j0+q]; shl[q]=sh2[j0+q]; acc[q]=0.f; }
    for (int mt = 0; mt < MM; mt += 64) {
        int m = mt + lane*2;
        float aw0 = aw[m], aw1 = aw[m+1];
        #pragma unroll
        for (int q = 0; q < 4; q++) {
            __half2 hv = *(const __half2*)&g_h2[((size_t)bn*O2 + j0+q)*MM + m];
            float2 fv = __half22float2(hv);
            float y0 = fmaxf(fmaf(scl[q], fv.x, shl[q]), 0.0f);
            float y1 = fmaxf(fmaf(scl[q], fv.y, shl[q]), 0.0f);
            acc[q] += aw0*y0 + aw1*y1;
        }
    }
    #pragma unroll
    for (int q = 0; q < 4; q++) {
        float s = acc[q];
        #pragma unroll
        for (int off = 16; off > 0; off >>= 1) s += __shfl_down_sync(0xffffffffu, s, off);
        if (lane == 0) g_attv[bn*O2 + j0+q] = s;
    }
}

__global__ void k_head(const float* __restrict__ M1w, const float* __restrict__ M1b) {
    int bn = blockIdx.x;
    int j = threadIdx.x;
    float s = M1b[j];
    #pragma unroll 8
    for (int c = 0; c < O2; c++) s += g_attv[bn*O2+c]*M1w[c*O3+j];
    g_tv[bn*O3+j] = s;
    atomicAdd(&g_stat3[j], s);
    atomicAdd(&g_stat3[O3+j], s*s);
}

__global__ void k_fin3(const float* __restrict__ M1g, const float* __restrict__ M1be) {
    int j = threadIdx.x;
    float mean = g_stat3[j]/CNT3;
    float var  = g_stat3[O3+j]/CNT3 - mean*mean;
    float sc = M1g[j]*rsqrtf(var + EPS_BN);
    g_bn3[j] = sc; g_bn3[O3+j] = M1be[j] - mean*sc;
}

__global__ void k_final(const float* __restrict__ M2w, const float* __restrict__ M2b,
                        float* __restrict__ out) {
    int bn = blockIdx.x*128 + threadIdx.x;
    float l0 = M2b[0], l1 = M2b[1];
    #pragma unroll 8
    for (int c = 0; c < O3; c++) {
        float y = fmaxf(fmaf(g_bn3[c], g_tv[bn*O3+c], g_bn3[O3+c]), 0.0f);
        l0 += y*M2w[c*2+0];
        l1 += y*M2w[c*2+1];
    }
    out[bn*2+0] = l0;
    out[bn*2+1] = l1;
}

extern "C" void kernel_launch(void* const* d_in, const int* in_sizes, int n_in,
                              void* d_out, int out_size) {
    const float* wxyz = (const float*)d_in[0];
    const float* wpts = (const float*)d_in[1];
    const float* RF3  = (const float*)d_in[2];
    const float* RF3i = (const float*)d_in[3];
    const float* lz   = (const float*)d_in[4];
    const float* W1   = (const float*)d_in[5];
    const float* b1   = (const float*)d_in[6];
    const float* g1   = (const float*)d_in[7];
    const float* be1  = (const float*)d_in[8];
    const float* W2   = (const float*)d_in[9];
    const float* b2   = (const float*)d_in[10];
    const float* g2   = (const float*)d_in[11];
    const float* be2  = (const float*)d_in[12];
    const float* M1w  = (const float*)d_in[13];
    const float* M1b  = (const float*)d_in[14];
    const float* M1g  = (const float*)d_in[15];
    const float* M1be = (const float*)d_in[16];
    const float* M2w  = (const float*)d_in[17];
    const float* M2b  = (const float*)d_in[18];
    float* out = (float*)d_out;

    cudaFuncSetAttribute(k_gemm2w, cudaFuncAttributeMaxDynamicSharedMemorySize, WSM_TOT);

    k_zero<<<10, 256>>>();
    k_prep_dst<<<BB*MM, 128>>>(RF3, RF3i, W1);
    k_prep_src<<<BB*NN, 128>>>(wxyz, wpts, lz, W1, b1);
    k_cos2<<<BB*64, 256>>>();
    k_rowmax<<<ROWS/8, 256>>>();
    k_colpart<<<64, 128>>>(wxyz);
    k_colfin<<<8, 128>>>();
    k_rowsums<<<ROWS/8, 256>>>(wxyz);
    k_redAD<<<32, 128>>>();
    k_fin1<<<1, 128>>>(W1, g1, be1);
    k_rescale<<<(2*ROWS*O1)/256, 256>>>();
    k_gemm2w<<<BB*NN, 256, WSM_TOT>>>(W2, b2, wxyz);
    k_fin2<<<1, 64>>>(g2, be2);
    k_att<<<BB*NN, 512>>>();
    k_head<<<ROWS, 32>>>(M1w, M1b);
    k_fin3<<<1, 32>>>(M1g, M1be);
    k_final<<<ROWS/128, 128>>>(M2w, M2b, out);
}

// round 16
// speedup vs baseline: 1.1309x; 1.0009x over previous
#include <cuda_runtime.h>
#include <cuda_fp16.h>
#include <mma.h>
#include <math.h>

using namespace nvcuda;

#define BB 2
#define NN 512
#define MM 512
#define CC 64
#define O1 128
#define O2 64
#define O3 32
#define ROWS (BB*NN)
#define CNT1 524288.0f
#define CNT3 1024.0f
#define EPS_BN 1e-5f

__device__ float g_srcn[BB*NN*CC];
__device__ float g_dstn[BB*MM*CC];
__device__ float g_A[BB*NN*O1];
__device__ float g_D[BB*MM*O1];
__device__ float g_idxy[BB*MM*2];
__device__ float g_cos[BB*NN*MM];
__device__ int   g_rowmaxi[BB*NN];
__device__ float g_colinv[BB*MM];
__device__ float g_bn1[2*O1];
__device__ float g_w1s[3*O1];
__device__ __half g_h2[(size_t)ROWS*O2*MM];
__device__ float g_stat2[2*O2];
__device__ float g_bn2[2*O2];
__device__ float g_attv[ROWS*O2];
__device__ float g_tv[ROWS*O3];
__device__ float g_stat3[2*O3];
__device__ float g_bn3[2*O3];
__device__ float g_jE[BB*NN], g_jS1[BB*NN], g_jS2[BB*NN];
__device__ float g_cE[BB*MM], g_cS1[BB*MM], g_cS2[BB*MM];
__device__ float g_cpart[8*BB*MM*4];
__device__ float g_jsc[9];
__device__ float g_redA[BB*5*O1];
__device__ float g_redD[BB*5*O1];

__device__ __forceinline__ float dec_rowinv(int e) {
    return 1.0f/((__int_as_float(e) - 2.0f) + 1e-6f);
}

__global__ void k_zero() {
    int t = blockIdx.x*256 + threadIdx.x;
    if (t < BB*5*O1) { g_redA[t] = 0.f; g_redD[t] = 0.f; }
    if (t < ROWS) g_rowmaxi[t] = 0;
    if (t < 9) g_jsc[t] = 0.f;
    if (t < 2*O2) g_stat2[t] = 0.f;
    if (t < 2*O3) g_stat3[t] = 0.f;
}

__global__ void k_prep_dst(const float* __restrict__ RF3, const float* __restrict__ RF3i,
                           const float* __restrict__ W1) {
    int b = blockIdx.x / MM, m = blockIdx.x % MM;
    int t = threadIdx.x; // 128
    __shared__ float rf[CC], red[CC], sidx[3];
    if (t < CC) { float v = RF3[((size_t)(b*CC + t))*MM + m]; rf[t] = v; red[t] = v*v; }
    if (t >= CC && t < CC+3) sidx[t-CC] = RF3i[((size_t)(b*3 + (t-CC)))*MM + m];
    __syncthreads();
    if (t < 32) red[t] += red[t+32];
    __syncthreads();
    if (t == 0) {
        float s = 0.f;
        #pragma unroll
        for (int i = 0; i < 32; i++) s += red[i];
        red[0] = 1.0f / fmaxf(sqrtf(s), 1e-12f);
    }
    __syncthreads();
    float inv = red[0];
    if (t < CC) g_dstn[(b*MM+m)*CC + t] = rf[t]*inv;
    if (t < 2)  g_idxy[(b*MM+m)*2 + t] = sidx[t];
    float ix = sidx[0], iy = sidx[1];
    int o = t;
    float d = ix*(W1[5*O1+o] - W1[7*O1+o]) + iy*(W1[6*O1+o] - W1[8*O1+o]);
    #pragma unroll 8
    for (int c = 0; c < CC; c++) d += rf[c]*W1[(10+CC+c)*O1 + o];
    g_D[(b*MM+m)*O1 + o] = d;
}

__global__ void k_prep_src(const float* __restrict__ wxyz, const float* __restrict__ wpts,
                           const float* __restrict__ lz, const float* __restrict__ W1,
                           const float* __restrict__ b1) {
    int b = blockIdx.x / NN, n = blockIdx.x % NN;
    int t = threadIdx.x; // 128
    __shared__ float wp[CC], red[CC], sx[4];
    if (t < CC) { float v = wpts[(b*NN+n)*CC + t]; wp[t] = v; red[t] = v*v; }
    if (t >= CC && t < CC+3) sx[t-CC] = wxyz[(b*NN+n)*3 + (t-CC)];
    if (t == CC+3) sx[3] = lz[b*NN+n];
    __syncthreads();
    if (t < 32) red[t] += red[t+32];
    __syncthreads();
    if (t == 0) {
        float s = 0.f;
        #pragma unroll
        for (int i = 0; i < 32; i++) s += red[i];
        red[0] = 1.0f / fmaxf(sqrtf(s), 1e-12f);
    }
    __syncthreads();
    float inv = red[0];
    if (t < CC) g_srcn[(b*NN+n)*CC + t] = wp[t]*inv;
    float l = sx[3];
    int o = t;
    float a = sx[0]*l*W1[0*O1+o] + sx[1]*l*W1[1*O1+o] + sx[2]*l*W1[2*O1+o]
            + wp[0]*W1[3*O1+o] + wp[1]*W1[4*O1+o]
            + sx[0]*W1[7*O1+o] + sx[1]*W1[8*O1+o] + b1[o];
    #pragma unroll 8
    for (int c = 0; c < CC; c++) a += wp[c]*W1[(10+c)*O1 + o];
    g_A[(b*NN+n)*O1 + o] = a;
}

// 32n x 64m tiles, 256 blocks; fused row-max via encoded atomicMax
__global__ void __launch_bounds__(256) k_cos2() {
    int blk = blockIdx.x;                 // b*128 + nt*8 + mt
    int b = blk >> 7, nt = (blk >> 3) & 15, mt = blk & 7;
    __shared__ float sA[64*33];           // [k][n]
    __shared__ float sB[64*65];           // [k][m]
    int t = threadIdx.x;
    for (int i = t; i < 32*64; i += 256) {
        int r = i >> 6, c = i & 63;       // r = n-local (0..31)
        sA[c*33 + r] = g_srcn[(b*NN + nt*32 + r)*CC + c];
    }
    for (int i = t; i < 64*64; i += 256) {
        int r = i >> 6, c = i & 63;
        sB[c*65 + r] = g_dstn[(b*MM + mt*64 + r)*CC + c];
    }
    __syncthreads();
    int tx = t & 15, ty = t >> 4;
    float acc[2][4];
    #pragma unroll
    for (int i = 0; i < 2; i++)
        #pragma unroll
        for (int j = 0; j < 4; j++) acc[i][j] = 0.f;
    #pragma unroll 4
    for (int k = 0; k < 64; k++) {
        float ra[2], rb[4];
        #pragma unroll
        for (int i = 0; i < 2; i++) ra[i] = sA[k*33 + ty + 16*i];
        #pragma unroll
        for (int j = 0; j < 4; j++) rb[j] = sB[k*65 + tx + 16*j];
        #pragma unroll
        for (int i = 0; i < 2; i++)
            #pragma unroll
            for (int j = 0; j < 4; j++) acc[i][j] += ra[i]*rb[j];
    }
    #pragma unroll
    for (int i = 0; i < 2; i++) {
        int n = nt*32 + ty + 16*i;
        float rmx = -1e30f;
        #pragma unroll
        for (int j = 0; j < 4; j++) {
            int m = mt*64 + tx + 16*j;
            g_cos[((size_t)(b*NN+n))*MM + m] = acc[i][j];
            rmx = fmaxf(rmx, acc[i][j]);
        }
        #pragma unroll
        for (int off = 8; off > 0; off >>= 1)
            rmx = fmaxf(rmx, __shfl_xor_sync(0xffffffffu, rmx, off));
        if (tx == 0) atomicMax(&g_rowmaxi[b*NN+n], __float_as_int(rmx + 2.0f));
    }
}

__global__ void k_colpart(const float* __restrict__ wxyz) {
    int blk = blockIdx.x;
    int b = blk >> 5, mc = (blk >> 3) & 3, nc = blk & 7;
    int t = threadIdx.x;
    int m = mc*128 + t;
    float ix = g_idxy[(b*MM+m)*2], iy = g_idxy[(b*MM+m)*2+1];
    float pmax = -1e30f, pE = 0.f, pS1 = 0.f, pCV = 0.f;
    for (int n = nc*64; n < nc*64+64; n++) {
        int bn = b*NN + n;
        float wx = wxyz[bn*3], wy = wxyz[bn*3+1];
        float ex = wx-ix, ey = wy-iy;
        pE += sqrtf(ex*ex + ey*ey);
        float cv = g_cos[(size_t)bn*MM + m];
        pmax = fmaxf(pmax, cv);
        pS1 += cv*dec_rowinv(g_rowmaxi[bn]);
        pCV += cv;
    }
    int base = ((nc*BB + b)*MM + m)*4;
    g_cpart[base+0] = pmax; g_cpart[base+1] = pE;
    g_cpart[base+2] = pS1;  g_cpart[base+3] = pCV;
}

__global__ void k_colfin() {
    int id = blockIdx.x*128 + threadIdx.x;
    int b = id >> 9, m = id & (MM-1);
    float mx = -1e30f, sE = 0.f, s1 = 0.f, cvs = 0.f;
    #pragma unroll
    for (int nc = 0; nc < 8; nc++) {
        int base = ((nc*BB + b)*MM + m)*4;
        mx = fmaxf(mx, g_cpart[base]);
        sE += g_cpart[base+1]; s1 += g_cpart[base+2]; cvs += g_cpart[base+3];
    }
    float cinv = 1.0f/(mx + 1e-10f);
    g_colinv[b*MM+m] = cinv;
    g_cE[b*MM+m] = sE; g_cS1[b*MM+m] = s1; g_cS2[b*MM+m] = cvs*cinv;
}

__global__ void __launch_bounds__(256) k_rowsums(const float* __restrict__ wxyz) {
    int bn = (blockIdx.x << 3) + (threadIdx.x >> 5);
    int lane = threadIdx.x & 31;
    int b = bn >> 9;
    float wx = wxyz[bn*3], wy = wxyz[bn*3+1];
    float invr = dec_rowinv(g_rowmaxi[bn]);
    float v[9] = {0,0,0,0,0,0,0,0,0};
    for (int m = lane; m < MM; m += 32) {
        float ix = g_idxy[(b*MM+m)*2], iy = g_idxy[(b*MM+m)*2+1];
        float ex = wx-ix, ey = wy-iy;
        float en = sqrtf(ex*ex + ey*ey);
        float cv = g_cos[(size_t)bn*MM + m];
        float s1 = cv*invr, s2 = cv*g_colinv[b*MM+m];
        v[0]+=en; v[1]+=s1; v[2]+=s2;
        v[3]+=en*en; v[4]+=s1*s1; v[5]+=s2*s2;
        v[6]+=en*s1; v[7]+=en*s2; v[8]+=s1*s2;
    }
    #pragma unroll
    for (int q = 0; q < 9; q++)
        #pragma unroll
        for (int off = 16; off > 0; off >>= 1) v[q] += __shfl_down_sync(0xffffffffu, v[q], off);
    if (lane == 0) {
        g_jE[bn] = v[0]; g_jS1[bn] = v[1]; g_jS2[bn] = v[2];
        #pragma unroll
        for (int q = 0; q < 9; q++) atomicAdd(&g_jsc[q], v[q]);
    }
}

__global__ void k_redAD() {
    int q = blockIdx.x;
    int o = threadIdx.x;
    if (q < 16) {
        int b = q >> 3, ch = q & 7;
        float sA=0.f, sA2=0.f, aE=0.f, aS1=0.f, aS2=0.f;
        for (int n = ch*64; n < ch*64+64; n++) {
            float a = g_A[(b*NN+n)*O1 + o];
            sA += a; sA2 += a*a;
            aE  += a*g_jE[b*NN+n];
            aS1 += a*g_jS1[b*NN+n];
            aS2 += a*g_jS2[b*NN+n];
        }
        atomicAdd(&g_redA[(b*5+0)*O1+o], sA);
        atomicAdd(&g_redA[(b*5+1)*O1+o], sA2);
        atomicAdd(&g_redA[(b*5+2)*O1+o], aE);
        atomicAdd(&g_redA[(b*5+3)*O1+o], aS1);
        atomicAdd(&g_redA[(b*5+4)*O1+o], aS2);
    } else {
        int b = (q-16) >> 3, ch = (q-16) & 7;
        float sD=0.f, sD2=0.f, dE=0.f, dS1=0.f, dS2=0.f;
        for (int m = ch*64; m < ch*64+64; m++) {
            float d = g_D[(b*MM+m)*O1 + o];
            sD += d; sD2 += d*d;
            dE  += d*g_cE[b*MM+m];
            dS1 += d*g_cS1[b*MM+m];
            dS2 += d*g_cS2[b*MM+m];
        }
        atomicAdd(&g_redD[(b*5+0)*O1+o], sD);
        atomicAdd(&g_redD[(b*5+1)*O1+o], sD2);
        atomicAdd(&g_redD[(b*5+2)*O1+o], dE);
        atomicAdd(&g_redD[(b*5+3)*O1+o], dS1);
        atomicAdd(&g_redD[(b*5+4)*O1+o], dS2);
    }
}

__global__ void k_fin1(const float* __restrict__ W1, const float* __restrict__ g1,
                       const float* __restrict__ be1) {
    int o = threadIdx.x;
    float w9 = W1[9*O1+o], wa = W1[138*O1+o], wb = W1[139*O1+o];
    float SH = 0.f, SH2 = 0.f;
    #pragma unroll
    for (int b = 0; b < BB; b++) {
        float sA = g_redA[(b*5+0)*O1+o], sA2 = g_redA[(b*5+1)*O1+o];
        float aE = g_redA[(b*5+2)*O1+o], aS1 = g_redA[(b*5+3)*O1+o], aS2 = g_redA[(b*5+4)*O1+o];
        float sD = g_redD[(b*5+0)*O1+o], sD2 = g_redD[(b*5+1)*O1+o];
        float dE = g_redD[(b*5+2)*O1+o], dS1 = g_redD[(b*5+3)*O1+o], dS2 = g_redD[(b*5+4)*O1+o];
        SH  += (float)MM*sA + (float)NN*sD;
        SH2 += (float)MM*sA2 + (float)NN*sD2 + 2.f*sA*sD
             + 2.f*(w9*aE + wa*aS1 + wb*aS2)
             + 2.f*(w9*dE + wa*dS1 + wb*dS2);
    }
    SH  += w9*g_jsc[0] + wa*g_jsc[1] + wb*g_jsc[2];
    SH2 += w9*w9*g_jsc[3] + wa*wa*g_jsc[4] + wb*wb*g_jsc[5]
         + 2.f*w9*wa*g_jsc[6] + 2.f*w9*wb*g_jsc[7] + 2.f*wa*wb*g_jsc[8];
    float mean = SH/CNT1;
    float var  = SH2/CNT1 - mean*mean;
    float sc = g1[o]*rsqrtf(var + EPS_BN);
    float sh = be1[o] - mean*sc;
    g_bn1[o] = sc; g_bn1[O1+o] = sh;
    g_w1s[o]      = w9*sc;
    g_w1s[O1+o]   = wa*sc;
    g_w1s[2*O1+o] = wb*sc;
}

// ---- wmma GEMM2 with BN1 folded inline (no k_rescale) ----
#define WSM_W2  0
#define WSM_R   16384
#define WSM_OUT 51200
#define WSM_ESS 84992
#define WSM_ST  91136
#define WSM_B2  91648
#define WSM_TOT 91904
#define LDR 136
#define LDO 132

__global__ void __launch_bounds__(256)
k_gemm2w(const float* __restrict__ W2, const float* __restrict__ b2p,
         const float* __restrict__ wxyz) {
    extern __shared__ char smc[];
    __half* s_w2h = (__half*)(smc + WSM_W2);
    __half* s_r   = (__half*)(smc + WSM_R);
    float* s_out  = (float*)(smc + WSM_OUT);
    float* s_ess  = (float*)(smc + WSM_ESS);
    float* s_stat = (float*)(smc + WSM_ST);
    float* s_b2   = (float*)(smc + WSM_B2);
    int b = blockIdx.x / NN, n = blockIdx.x % NN;
    int bn = b*NN + n;
    int t = threadIdx.x;
    int wid = t >> 5;

    for (int i = t; i < O1*O2; i += 256) s_w2h[i] = __float2half_rn(W2[i]);
    float wx = wxyz[bn*3+0], wy = wxyz[bn*3+1];
    float invr = dec_rowinv(g_rowmaxi[bn]);
    for (int m = t; m < MM; m += 256) {
        float ix = g_idxy[(b*MM+m)*2+0], iy = g_idxy[(b*MM+m)*2+1];
        float ex = wx-ix, ey = wy-iy;
        s_ess[m] = sqrtf(ex*ex + ey*ey);
        float cv = g_cos[((size_t)bn)*MM + m];
        s_ess[MM+m]   = cv*invr;
        s_ess[2*MM+m] = cv*g_colinv[b*MM+m];
    }
    if (t < O2) s_b2[t] = b2p[t];
    if (t < 2*O2) s_stat[t] = 0.f;

    int o = t & (O1-1), half_ = t >> 7;
    float sc1 = g_bn1[o];
    float base = fmaf(g_A[bn*O1 + o], sc1, g_bn1[O1+o]);
    float wn = g_w1s[o], w1s = g_w1s[O1+o], w2sv = g_w1s[2*O1+o];
    int js = t & 63, grp = t >> 6;
    float ssum = 0.f, ssq = 0.f;
    __syncthreads();
    float bbj = s_b2[js];

    for (int mt = 0; mt < 4; mt++) {
        const float* Dp = &g_D[(size_t)(b*MM + mt*128 + half_*64)*O1 + o];
        #pragma unroll 4
        for (int i = 0; i < 64; i++) {
            int ml = half_*64 + i, m = mt*128 + ml;
            float tmp = fmaf(s_ess[m], wn, base);
            tmp = fmaf(s_ess[MM+m], w1s, tmp);
            tmp = fmaf(s_ess[2*MM+m], w2sv, tmp);
            float h = fmaf(Dp[(size_t)i*O1], sc1, tmp);
            s_r[ml*LDR + o] = __float2half_rn(fmaxf(h, 0.0f));
        }
        __syncthreads();

        wmma::fragment<wmma::accumulator, 16, 16, 16, float> cf[4];
        #pragma unroll
        for (int jb = 0; jb < 4; jb++) wmma::fill_fragment(cf[jb], 0.0f);
        #pragma unroll
        for (int ks = 0; ks < 8; ks++) {
            wmma::fragment<wmma::matrix_a, 16, 16, 16, __half, wmma::row_major> af;
            wmma::load_matrix_sync(af, &s_r[(wid*16)*LDR + ks*16], LDR);
            #pragma unroll
            for (int jb = 0; jb < 4; jb++) {
                wmma::fragment<wmma::matrix_b, 16, 16, 16, __half, wmma::row_major> bf;
                wmma::load_matrix_sync(bf, &s_w2h[(ks*16)*O2 + jb*16], O2);
                wmma::mma_sync(cf[jb], af, bf, cf[jb]);
            }
        }
        #pragma unroll
        for (int jb = 0; jb < 4; jb++)
            wmma::store_matrix_sync(&s_out[(jb*16)*LDO + wid*16], cf[jb], LDO, wmma::mem_col_major);
        __syncthreads();

        #pragma unroll
        for (int i = 0; i < 16; i++) {
            int idx = t + i*256;
            int j = idx >> 6;
            int m2 = (idx & 63)*2;
            float2 v = *(const float2*)&s_out[j*LDO + m2];
            float bb = s_b2[j];
            *(__half2*)&g_h2[((size_t)bn*O2 + j)*MM + mt*128 + m2] = __floats2half2_rn(v.x + bb, v.y + bb);
        }
        #pragma unroll
        for (int ii = 0; ii < 16; ii++) {
            int m2 = grp*32 + ii*2;
            float2 v = *(const float2*)&s_out[js*LDO + m2];
            float v0 = v.x + bbj, v1 = v.y + bbj;
            ssum += v0 + v1; ssq += v0*v0 + v1*v1;
        }
        __syncthreads();
    }
    atomicAdd(&s_stat[js], ssum);
    atomicAdd(&s_stat[O2+js], ssq);
    __syncthreads();
    if (t < 2*O2) atomicAdd(&g_stat2[t], s_stat[t]);
}

__global__ void k_fin2(const float* __restrict__ g2, const float* __restrict__ be2) {
    int j = threadIdx.x;
    float mean = g_stat2[j]/CNT1;
    float var  = g_stat2[O2+j]/CNT1 - mean*mean;
    float sc = g2[j]*rsqrtf(var + EPS_BN);
    g_bn2[j] = sc; g_bn2[O2+j] = be2[j] - mean*sc;
}

__global__ void k_att() {
    int bn = blockIdx.x;
    int t = threadIdx.x; // 512
    __shared__ float sc2[O2], sh2[O2], aw[MM], red[512];
    if (t < O2) { sc2[t] = g_bn2[t]; sh2[t] = g_bn2[O2+t]; }
    __syncthreads();
    float mx = -1e30f;
    #pragma unroll 8
    for (int j = 0; j < O2; j++) {
        float v = __half2float(g_h2[((size_t)bn*O2 + j)*MM + t]);
        float y = fmaxf(fmaf(sc2[j], v, sh2[j]), 0.0f);
        mx = fmaxf(mx, y);
    }
    red[t] = mx;
    __syncthreads();
    for (int s = 256; s > 0; s >>= 1) { if (t < s) red[t] = fmaxf(red[t], red[t+s]); __syncthreads(); }
    float mall = red[0];
    __syncthreads();
    float e = expf(mx - mall);
    red[t] = e;
    __syncthreads();
    for (int s = 256; s > 0; s >>= 1) { if (t < s) red[t] += red[t+s]; __syncthreads(); }
    float inv = 1.0f/red[0];
    aw[t] = e*inv;
    __syncthreads();

    int w = t >> 5, lane = t & 31;
    int j0 = w*4;
    float scl[4], shl[4], acc[4];
    #pragma unroll
    for (int q = 0; q < 4; q++) { scl[q]=sc2[j0+q]; shl[q]=sh2[j0+q]; acc[q]=0.f; }
    for (int mt = 0; mt < MM; mt += 64) {
        int m = mt + lane*2;
        float aw0 = aw[m], aw1 = aw[m+1];
        #pragma unroll
        for (int q = 0; q < 4; q++) {
            __half2 hv = *(const __half2*)&g_h2[((size_t)bn*O2 + j0+q)*MM + m];
            float2 fv = __half22float2(hv);
            float y0 = fmaxf(fmaf(scl[q], fv.x, shl[q]), 0.0f);
            float y1 = fmaxf(fmaf(scl[q], fv.y, shl[q]), 0.0f);
            acc[q] += aw0*y0 + aw1*y1;
        }
    }
    #pragma unroll
    for (int q = 0; q < 4; q++) {
        float s = acc[q];
        #pragma unroll
        for (int off = 16; off > 0; off >>= 1) s += __shfl_down_sync(0xffffffffu, s, off);
        if (lane == 0) g_attv[bn*O2 + j0+q] = s;
    }
}

__global__ void k_head(const float* __restrict__ M1w, const float* __restrict__ M1b) {
    int bn = blockIdx.x;
    int j = threadIdx.x;
    float s = M1b[j];
    #pragma unroll 8
    for (int c = 0; c < O2; c++) s += g_attv[bn*O2+c]*M1w[c*O3+j];
    g_tv[bn*O3+j] = s;
    atomicAdd(&g_stat3[j], s);
    atomicAdd(&g_stat3[O3+j], s*s);
}

__global__ void k_fin3(const float* __restrict__ M1g, const float* __restrict__ M1be) {
    int j = threadIdx.x;
    float mean = g_stat3[j]/CNT3;
    float var  = g_stat3[O3+j]/CNT3 - mean*mean;
    float sc = M1g[j]*rsqrtf(var + EPS_BN);
    g_bn3[j] = sc; g_bn3[O3+j] = M1be[j] - mean*sc;
}

__global__ void k_final(const float* __restrict__ M2w, const float* __restrict__ M2b,
                        float* __restrict__ out) {
    int bn = blockIdx.x*128 + threadIdx.x;
    float l0 = M2b[0], l1 = M2b[1];
    #pragma unroll 8
    for (int c = 0; c < O3; c++) {
        float y = fmaxf(fmaf(g_bn3[c], g_tv[bn*O3+c], g_bn3[O3+c]), 0.0f);
        l0 += y*M2w[c*2+0];
        l1 += y*M2w[c*2+1];
    }
    out[bn*2+0] = l0;
    out[bn*2+1] = l1;
}

extern "C" void kernel_launch(void* const* d_in, const int* in_sizes, int n_in,
                              void* d_out, int out_size) {
    const float* wxyz = (const float*)d_in[0];
    const float* wpts = (const float*)d_in[1];
    const float* RF3  = (const float*)d_in[2];
    const float* RF3i = (const float*)d_in[3];
    const float* lz   = (const float*)d_in[4];
    const float* W1   = (const float*)d_in[5];
    const float* b1   = (const float*)d_in[6];
    const float* g1   = (const float*)d_in[7];
    const float* be1  = (const float*)d_in[8];
    const float* W2   = (const float*)d_in[9];
    const float* b2   = (const float*)d_in[10];
    const float* g2   = (const float*)d_in[11];
    const float* be2  = (const float*)d_in[12];
    const float* M1w  = (const float*)d_in[13];
    const float* M1b  = (const float*)d_in[14];
    const float* M1g  = (const float*)d_in[15];
    const float* M1be = (const float*)d_in[16];
    const float* M2w  = (const float*)d_in[17];
    const float* M2b  = (const float*)d_in[18];
    float* out = (float*)d_out;

    cudaFuncSetAttribute(k_gemm2w, cudaFuncAttributeMaxDynamicSharedMemorySize, WSM_TOT);

    k_zero<<<10, 256>>>();
    k_prep_dst<<<BB*MM, 128>>>(RF3, RF3i, W1);
    k_prep_src<<<BB*NN, 128>>>(wxyz, wpts, lz, W1, b1);
    k_cos2<<<BB*128, 256>>>();
    k_colpart<<<64, 128>>>(wxyz);
    k_colfin<<<8, 128>>>();
    k_rowsums<<<ROWS/8, 256>>>(wxyz);
    k_redAD<<<32, 128>>>();
    k_fin1<<<1, 128>>>(W1, g1, be1);
    k_gemm2w<<<BB*NN, 256, WSM_TOT>>>(W2, b2, wxyz);
    k_fin2<<<1, 64>>>(g2, be2);
    k_att<<<BB*NN, 512>>>();
    k_head<<<ROWS, 32>>>(M1w, M1b);
    k_fin3<<<1, 32>>>(M1g, M1be);
    k_final<<<ROWS/128, 128>>>(M2w, M2b, out);
}